// round 17
// baseline (speedup 1.0000x reference)
#include <cuda_runtime.h>
#include <cuda_bf16.h>

// Two-node pipeline with a warp-cooperative, spatially-ordered query phase.
//   K1 build : insert bodies into parity-selected cell grid (32x256); last
//              finishing block bumps g_epoch (graph edge publishes to K2).
//   K2: phase1 — each WARP owns ~12 contiguous grid cells, ballot-compacts
//              its occupied slots into shared, lanes query spatially adjacent
//              bodies (coalesced, L1-resident ring loads, uniform counts),
//              and scatter per-body packed counts + precomputed hit records
//              (rank, hrank, delta) keyed by body index.
//       counted full barrier (uniform arrival; cleanup in the wait window)
//       phase2 — gid-ordered: coalesced g_pc loads, packed block scan,
//              tagged single-word decoupled lookback, cutoff checks, atomics.
//
// N=8192, BOX=112, radii in [0.5,1.0) -> rsum < 2.0 -> grid cell 2.0 (56x56);
// all AABB-overlapping pairs lie within the +-1 cell ring.
// Reference semantics reproduced exactly: row-major ascending (i,j) candidate
// order, cutoffs limit_broad=4N (candidates) and limit_narrow=N (hits).

#define MAXN  8192
#define MAXB  (4 * MAXN)
#define GDIM  56
#define NCELL (GDIM * GDIM)
#define CAPC  20            // bodies/cell cap (avg 2.6; Poisson tail safe)
#define CAPR  32            // candidates/row cap (avg ~8; tail safe)
#define CAPH  16            // stored hits per row (avg ~1-2; tail safe)
#define NBLK  32
#define NTPB  256
#define NTH   (NBLK * NTPB)
#define NWARP (NTH / 32)    // 256 warps; ~12.25 cells each
#define MAXPW 280           // max slots per warp (13 cells * 20 + margin)

typedef unsigned long long ull;

__device__ unsigned     g_done      = 0;       // K1 completion counter
__device__ unsigned     g_epoch     = 0;       // +1 per launch by K1 last block
__device__ unsigned     g_mid_cnt   = 0;       // K2 mid-barrier counter
__device__ unsigned     g_mid_epoch = 0;       // +1 per launch at mid barrier
__device__ int          g_cellcnt[2][NCELL];   // parity double buffer
__device__ float4       g_cellslot[2][NCELL * CAPC];
__device__ int          g_pc[MAXN];            // (cnt<<8)|hitcnt per body
__device__ float4       g_rec[MAXN * CAPH];    // ddx, ddy, packed(jv|rank|hrank)
__device__ volatile ull g_flag[NBLK];          // (tag<<32)|(cnt<<16)|hit

// ---------------------------------------------------------------------------
__global__ void __launch_bounds__(NTPB)
build_kernel(const float2* __restrict__ c, const float* __restrict__ r,
             float* __restrict__ out, int n) {
    const int gid = blockIdx.x * NTPB + threadIdx.x;
    const unsigned par = *(volatile unsigned*)&g_epoch & 1u;
    if (gid < n) {
        float2 ci = c[gid];
        float  ri = r[gid];
        ((float2*)out)[gid] = ci;
        int cx = min(GDIM - 1, max(0, (int)(ci.x * 0.5f)));
        int cy = min(GDIM - 1, max(0, (int)(ci.y * 0.5f)));
        int cell = cy * GDIM + cx;
        int slot = atomicAdd(&g_cellcnt[par][cell], 1);
        if (slot < CAPC)
            g_cellslot[par][cell * CAPC + slot] =
                make_float4(ci.x, ci.y, ri, __int_as_float(gid));
    }
    __syncthreads();
    if (threadIdx.x == 0) {
        __threadfence();
        unsigned old = atomicAdd(&g_done, 1u);
        if (old == gridDim.x - 1) {
            g_done = 0;
            atomicAdd(&g_epoch, 1u);      // K2 sees this via the graph edge
        }
    }
}

// ---------------------------------------------------------------------------
__global__ void __launch_bounds__(NTPB)
query_resolve_kernel(const float2* __restrict__ c, const float* __restrict__ r,
                     const int* __restrict__ d_lb, const int* __restrict__ d_ln,
                     float* __restrict__ out, int n) {
    __shared__ unsigned s_list[NTPB / 32][MAXPW];
    __shared__ ull s_ws[NTPB / 32 + 1];
    __shared__ ull s_pre;
    const int t    = threadIdx.x;
    const int lane = t & 31;
    const int wid  = t >> 5;
    const int bid  = blockIdx.x;
    const int gid  = bid * NTPB + t;

    const unsigned E   = *(volatile unsigned*)&g_epoch;
    const unsigned par = (E - 1u) & 1u;

    // ======== PHASE 1: warp-cooperative spatial query ========
    // warp wg owns cells [wg*NCELL/256, (wg+1)*NCELL/256)
    const int wg     = (bid * NTPB + t) >> 5;
    const int cellLo = (wg * NCELL) >> 8;
    const int cellHi = ((wg + 1) * NCELL) >> 8;
    const int span   = (cellHi - cellLo) * CAPC;
    const unsigned lmask = (1u << lane) - 1u;

    // gather occupied (cell,slot) into shared, compacted, cell-ordered
    int nb = 0;
    for (int base = 0; base < span; base += 32) {
        int idx = base + lane;
        bool occ = false;
        unsigned sl = 0;
        if (idx < span) {
            int cell = cellLo + idx / CAPC;
            int slot = idx - (idx / CAPC) * CAPC;
            int cc = min(g_cellcnt[par][cell], CAPC);
            occ = slot < cc;
            sl = (unsigned)(cell * CAPC + slot);
        }
        unsigned m = __ballot_sync(0xFFFFFFFFu, occ);
        if (occ) s_list[wid][nb + __popc(m & lmask)] = sl;
        nb += __popc(m);
    }

    // each lane queries spatially-adjacent bodies
    int keys[CAPR];
    float hdx[CAPR], hdy[CAPR], hrs[CAPR];
    for (int b = lane; b < nb; b += 32) {
        unsigned sl = s_list[wid][b];
        float4 body = g_cellslot[par][sl];
        const int   i  = __float_as_int(body.w);
        const float cix = body.x, ciy = body.y, ri = body.z;
        const int cell = sl / CAPC;
        const int cx = cell % GDIM, cy = cell / GDIM;

        unsigned hitmask = 0;
        int cnt = 0;
#define PROC(bb) do {                                                        \
        int   _j  = __float_as_int((bb).w);                                  \
        float _rs = ri + (bb).z;                                             \
        float _dx = (bb).x - cix;                                            \
        float _dy = (bb).y - ciy;                                            \
        bool  _acc = (_j > i) & (fabsf(_dx) <= _rs) & (fabsf(_dy) <= _rs);   \
        if (_acc) {                                                          \
            if (cnt < CAPR) {                                                \
                float _d2 = _dx * _dx + _dy * _dy + 1e-12f;                  \
                int _hit = (_d2 < _rs * _rs) ? 1 : 0;                        \
                keys[cnt] = (_j << 1) | _hit;                                \
                hitmask |= (unsigned)_hit << cnt;                            \
                hdx[cnt] = _dx; hdy[cnt] = _dy; hrs[cnt] = _rs;              \
            }                                                                \
            cnt++;                                                           \
        }                                                                    \
    } while (0)
        int cell9[9], cc9[9];
        #pragma unroll
        for (int s = 0; s < 9; s++) {
            int yy = cy + s / 3 - 1;
            int xx = cx + s % 3 - 1;
            bool v = (yy >= 0) & (yy < GDIM) & (xx >= 0) & (xx < GDIM);
            int cl = v ? yy * GDIM + xx : 0;
            cell9[s] = cl;
            cc9[s]   = v ? g_cellcnt[par][cl] : 0;
        }
        #pragma unroll
        for (int s = 0; s < 9; s++) {
            int cc = min(cc9[s], CAPC);
            const float4* bp = &g_cellslot[par][cell9[s] * CAPC];
            int q = 0;
            for (; q + 3 < cc; q += 4) {
                float4 b0 = bp[q], b1 = bp[q + 1], b2 = bp[q + 2], b3 = bp[q + 3];
                PROC(b0); PROC(b1); PROC(b2); PROC(b3);
            }
            for (; q < cc; q++) { float4 bb = bp[q]; PROC(bb); }
        }
#undef PROC
        if (cnt > CAPR) cnt = CAPR;
        const int hitcnt = __popc(hitmask);
        g_pc[i] = (cnt << 8) | hitcnt;

        // store hit records with per-row ranks (ascending-j order semantics)
        int nh = 0;
        unsigned m = hitmask;
        while (m && nh < CAPH) {
            int k = __ffs(m) - 1;
            m &= m - 1;
            int key = keys[k];
            int rank = 0, hrank = 0;
            #pragma unroll 4
            for (int q = 0; q < cnt; q++) {
                int kq = keys[q];
                int lt = (kq < key) ? 1 : 0;   // distinct j -> strict order
                rank  += lt;
                hrank += lt & kq;              // lt && hit-bit of q
            }
            float dx = hdx[k], dy = hdy[k], rs = hrs[k];
            float dist = sqrtf(dx * dx + dy * dy + 1e-12f);
            float sc = 0.5f * (rs - dist) / dist;
            int packed = ((key >> 1) << 10) | (rank << 5) | hrank;
            g_rec[i * CAPH + nh] =
                make_float4(sc * dx, sc * dy, __int_as_float(packed), 0.f);
            nh++;
        }
    }

    // ======== counted full barrier (uniform arrival) ========
    __threadfence();
    __syncthreads();
    if (t == 0) {
        unsigned old = atomicAdd(&g_mid_cnt, 1u);
        if (old == NBLK - 1) {
            g_mid_cnt = 0;
            __threadfence();
            atomicAdd(&g_mid_epoch, 1u);
        }
    }
    // useful work in the wait window
    const int limitb = min(*d_lb, MAXB);
    const int ln     = *d_ln;
    for (int idx = gid; idx < NCELL; idx += NTH) g_cellcnt[1 - par][idx] = 0;
    if (t == 0) {
        volatile unsigned* pe = &g_mid_epoch;
        while (*pe != E) __nanosleep(16);
    }
    __syncthreads();

    // ======== PHASE 2: gid-ordered scan + resolve ========
    int cnt = 0, hitcnt = 0;
    if (gid < n) {
        int v = g_pc[gid];                 // coalesced
        cnt = v >> 8;
        hitcnt = v & 0xFF;
    }
    ull v = ((ull)cnt << 32) | (unsigned)hitcnt;
    ull incl = v;
    #pragma unroll
    for (int o = 1; o < 32; o <<= 1) {
        ull x = __shfl_up_sync(0xFFFFFFFFu, incl, o);
        if (lane >= o) incl += x;
    }
    if (lane == 31) s_ws[wid] = incl;
    __syncthreads();
    if (wid == 0 && lane == 0) {
        ull run = 0;
        #pragma unroll
        for (int w = 0; w < NTPB / 32; w++) {
            ull x = s_ws[w];
            s_ws[w] = run;
            run += x;
        }
        s_ws[NTPB / 32] = run;
    }
    __syncthreads();
    ull excl = incl - v + s_ws[wid];

    if (t == 0) {
        ull btot = s_ws[NTPB / 32];
        g_flag[bid] = ((ull)E << 32) |
                      (((btot >> 32) & 0xFFFFull) << 16) |
                      (btot & 0xFFFFull);
        s_pre = 0;
    }
    __syncthreads();
    if (t < bid) {                         // decoupled lookback (partial order)
        ull w;
        do { w = g_flag[t]; } while ((unsigned)(w >> 32) != E);
        atomicAdd(&s_pre, (((w >> 16) & 0xFFFFull) << 32) | (w & 0xFFFFull));
    }
    __syncthreads();

    const ull tot  = s_pre + excl;
    const int offc = (int)(tot >> 32);
    const int offh = (int)(tot & 0xFFFFFFFFu);

    // Broad cutoff: sorted rank < limitb - offc. Dropped candidates are always
    // the highest ranks, so unmasked prefix sums stay exact for emitters.
    if (gid < n && hitcnt > 0 && offc < limitb) {
        const int survive = min(cnt, limitb - offc);
        const int nh = min(hitcnt, CAPH);
        float2 neg = make_float2(0.f, 0.f);
        for (int k = 0; k < nh; k++) {
            float4 rec = g_rec[gid * CAPH + k];
            int packed = __float_as_int(rec.z);
            int hrank  = packed & 31;
            int rank   = (packed >> 5) & 31;
            int jv     = packed >> 10;
            if (rank >= survive) continue;        // broad cutoff
            if (offh + hrank >= ln) continue;     // narrow cutoff
            neg.x -= rec.x; neg.y -= rec.y;
            atomicAdd(&out[2 * jv + 0], rec.x);
            atomicAdd(&out[2 * jv + 1], rec.y);
        }
        if (neg.x != 0.f || neg.y != 0.f) {
            atomicAdd(&out[2 * gid + 0], neg.x);
            atomicAdd(&out[2 * gid + 1], neg.y);
        }
    }
}

// ---------------------------------------------------------------------------
extern "C" void kernel_launch(void* const* d_in, const int* in_sizes, int n_in,
                              void* d_out, int out_size) {
    const float2* centers = (const float2*)d_in[0];
    const float*  radii   = (const float*)d_in[1];
    const int*    d_lb    = (const int*)d_in[2];
    const int*    d_ln    = (const int*)d_in[3];
    const int n = in_sizes[1];
    float* out = (float*)d_out;

    build_kernel<<<NBLK, NTPB>>>(centers, radii, out, n);
    query_resolve_kernel<<<NBLK, NTPB>>>(centers, radii, d_lb, d_ln, out, n);
}